// round 1
// baseline (speedup 1.0000x reference)
#include <cuda_runtime.h>

#define Bq 8
#define Nq 512
#define Fq 128
#define Hq 4
#define Uq 32
#define HU (Hq*Uq)

// Scratch (device globals: allocation-free)
__device__ float g_Hsrc[Bq*Hq*Nq*Uq];   // 2 MB
__device__ float g_Hdst[Bq*Hq*Nq*Uq];   // 2 MB
__device__ float g_Cdst[Bq*Hq*Nq];      // 64 KB

// ---------------------------------------------------------------------------
// Kernel 1: projections. h_src = inp @ W_src[h], h_dst = inp @ W_dst[h]
// grid (4096/64, H), 256 threads. Tile: 64 rows x 64 cols (32 src + 32 dst).
// ---------------------------------------------------------------------------
__global__ void proj_kernel(const float* __restrict__ inp,
                            const float* __restrict__ Wsrc,
                            const float* __restrict__ Wdst)
{
    extern __shared__ float sm[];
    float* sIn = sm;            // [64][132]  (pad 132 kills bank conflicts)
    float* sW  = sm + 64*132;   // [128][64]  (cols 0-31 src, 32-63 dst)

    const int tid  = threadIdx.x;
    const int h    = blockIdx.y;
    const int row0 = blockIdx.x * 64;   // global row in [0, B*N)

    for (int t = tid; t < 64*32; t += 256) {
        int r = t >> 5, c = t & 31;
        reinterpret_cast<float4*>(sIn + r*132)[c] =
            reinterpret_cast<const float4*>(inp + (row0 + r)*Fq)[c];
    }
    for (int t = tid; t < 128*8; t += 256) {
        int k = t >> 3, c = t & 7;
        reinterpret_cast<float4*>(sW + k*64)[c] =
            reinterpret_cast<const float4*>(Wsrc + (h*Fq + k)*Uq)[c];
        reinterpret_cast<float4*>(sW + k*64 + 32)[c] =
            reinterpret_cast<const float4*>(Wdst + (h*Fq + k)*Uq)[c];
    }
    __syncthreads();

    const int tx = tid & 15;   // col group: 4 cols
    const int ty = tid >> 4;   // row group: 4 rows
    float acc[4][4];
    #pragma unroll
    for (int r = 0; r < 4; r++)
        #pragma unroll
        for (int c = 0; c < 4; c++) acc[r][c] = 0.f;

    #pragma unroll 4
    for (int k = 0; k < 128; k++) {
        float4 cv = reinterpret_cast<const float4*>(sW + k*64)[tx];
        float rv0 = sIn[(ty*4+0)*132 + k];
        float rv1 = sIn[(ty*4+1)*132 + k];
        float rv2 = sIn[(ty*4+2)*132 + k];
        float rv3 = sIn[(ty*4+3)*132 + k];
        acc[0][0] = fmaf(rv0, cv.x, acc[0][0]); acc[0][1] = fmaf(rv0, cv.y, acc[0][1]);
        acc[0][2] = fmaf(rv0, cv.z, acc[0][2]); acc[0][3] = fmaf(rv0, cv.w, acc[0][3]);
        acc[1][0] = fmaf(rv1, cv.x, acc[1][0]); acc[1][1] = fmaf(rv1, cv.y, acc[1][1]);
        acc[1][2] = fmaf(rv1, cv.z, acc[1][2]); acc[1][3] = fmaf(rv1, cv.w, acc[1][3]);
        acc[2][0] = fmaf(rv2, cv.x, acc[2][0]); acc[2][1] = fmaf(rv2, cv.y, acc[2][1]);
        acc[2][2] = fmaf(rv2, cv.z, acc[2][2]); acc[2][3] = fmaf(rv2, cv.w, acc[2][3]);
        acc[3][0] = fmaf(rv3, cv.x, acc[3][0]); acc[3][1] = fmaf(rv3, cv.y, acc[3][1]);
        acc[3][2] = fmaf(rv3, cv.z, acc[3][2]); acc[3][3] = fmaf(rv3, cv.w, acc[3][3]);
    }

    const int b = row0 >> 9;          // 64 | 512 so whole tile is one batch
    float* dstp = (tx < 8) ? g_Hsrc : g_Hdst;
    const int c4 = tx & 7;
    #pragma unroll
    for (int r = 0; r < 4; r++) {
        int n = (row0 + ty*4 + r) & (Nq - 1);
        int ob = ((b*Hq + h)*Nq + n)*Uq;
        reinterpret_cast<float4*>(dstp + ob)[c4] =
            make_float4(acc[r][0], acc[r][1], acc[r][2], acc[r][3]);
    }
}

// ---------------------------------------------------------------------------
// Kernel 2: c_dst[b,h,j] = alpha * sum_u a[h,u] * h_dst[b,h,j,u]
// ---------------------------------------------------------------------------
__global__ void cdst_kernel(const float* __restrict__ Av)
{
    int idx = blockIdx.x * 256 + threadIdx.x;      // bh*512 + n, < 16384
    int h = (idx >> 9) & (Hq - 1);
    const float4* dr = reinterpret_cast<const float4*>(g_Hdst + idx*Uq);
    const float4* ar = reinterpret_cast<const float4*>(Av + h*Uq);
    float s = 0.f;
    #pragma unroll
    for (int q = 0; q < 8; q++) {
        float4 d = dr[q], a = ar[q];
        s += d.x*a.x + d.y*a.y + d.z*a.z + d.w*a.w;
    }
    g_Cdst[idx] = 0.2f * s;
}

// ---------------------------------------------------------------------------
// Kernel 3: fused attention.
// grid (4 i-blocks, 32 bh), 512 threads = 128 rows x 2 u-halves x 2 j-chunks.
// score'[i,j] = c_dst[j] + sum_u (0.8*a_u) * max(s_iu + d_ju, 0)
// (row-constant alpha*(a.s_i) dropped: cancels in softmax)
// ---------------------------------------------------------------------------
__global__ void __launch_bounds__(512, 1)
attn_kernel(const float* __restrict__ Av, float* __restrict__ out)
{
    extern __shared__ float sm[];
    float* sh_src = sm;               // [512][32]
    float* sh_dst = sm + Nq*Uq;       // [512][32]
    float* sh_c   = sm + 2*Nq*Uq;     // [512]

    const int tid = threadIdx.x;
    const int bh  = blockIdx.y;       // 0..31
    const int ib  = blockIdx.x;       // 0..3
    const int b   = bh >> 2;
    const int h   = bh & 3;

    const float* Hs = g_Hsrc + bh*Nq*Uq;
    const float* Hd = g_Hdst + bh*Nq*Uq;
    for (int t = tid; t < Nq*Uq/4; t += 512) {
        reinterpret_cast<float4*>(sh_src)[t] = reinterpret_cast<const float4*>(Hs)[t];
        reinterpret_cast<float4*>(sh_dst)[t] = reinterpret_cast<const float4*>(Hd)[t];
    }
    if (tid < Nq/4)
        reinterpret_cast<float4*>(sh_c)[tid] =
            reinterpret_cast<const float4*>(g_Cdst + bh*Nq)[tid];
    __syncthreads();

    const int chunk = tid >> 8;        // 0..1 : j in [chunk*256, +256)
    const int r2    = tid & 255;
    const int row   = r2 >> 1;         // 0..127
    const int uh    = r2 & 1;          // u-half; shfl partner = lane^1
    const int i     = ib*128 + row;
    const int ub    = uh*16;

    float s[16], a2[16];
    {
        const float4* sp = reinterpret_cast<const float4*>(sh_src + i*Uq + ub);
        const float4* ap = reinterpret_cast<const float4*>(Av + h*Uq + ub);
        #pragma unroll
        for (int q = 0; q < 4; q++) {
            float4 v = sp[q];
            s[q*4+0] = v.x; s[q*4+1] = v.y; s[q*4+2] = v.z; s[q*4+3] = v.w;
            float4 a = ap[q];
            a2[q*4+0] = 0.8f*a.x; a2[q*4+1] = 0.8f*a.y;
            a2[q*4+2] = 0.8f*a.z; a2[q*4+3] = 0.8f*a.w;
        }
    }

    float acc[16];
    #pragma unroll
    for (int u = 0; u < 16; u++) acc[u] = 0.f;
    float m = -1e30f, l = 0.f;
    const int j0 = chunk * 256;

    for (int jb = 0; jb < 256; jb += 8) {
        float sc[8];
        #pragma unroll
        for (int t = 0; t < 8; t++) {
            const int j = j0 + jb + t;
            const float4* dp = reinterpret_cast<const float4*>(sh_dst + j*Uq + ub);
            float p0 = 0.f, p1 = 0.f, p2 = 0.f, p3 = 0.f;
            #pragma unroll
            for (int q = 0; q < 4; q++) {
                float4 d = dp[q];
                p0 = fmaf(a2[q*4+0], fmaxf(s[q*4+0] + d.x, 0.f), p0);
                p1 = fmaf(a2[q*4+1], fmaxf(s[q*4+1] + d.y, 0.f), p1);
                p2 = fmaf(a2[q*4+2], fmaxf(s[q*4+2] + d.z, 0.f), p2);
                p3 = fmaf(a2[q*4+3], fmaxf(s[q*4+3] + d.w, 0.f), p3);
            }
            float ps = (p0 + p1) + (p2 + p3);
            ps += __shfl_xor_sync(0xffffffffu, ps, 1);
            sc[t] = ps + sh_c[j];
        }
        float bm = sc[0];
        #pragma unroll
        for (int t = 1; t < 8; t++) bm = fmaxf(bm, sc[t]);
        float mn = fmaxf(m, bm);
        float scale = __expf(m - mn);
        m = mn;
        l *= scale;
        #pragma unroll
        for (int u = 0; u < 16; u++) acc[u] *= scale;
        #pragma unroll
        for (int t = 0; t < 8; t++) {
            float p = __expf(sc[t] - m);
            l += p;
            const float4* vp =
                reinterpret_cast<const float4*>(sh_src + (j0 + jb + t)*Uq + ub);
            #pragma unroll
            for (int q = 0; q < 4; q++) {
                float4 v = vp[q];
                acc[q*4+0] = fmaf(p, v.x, acc[q*4+0]);
                acc[q*4+1] = fmaf(p, v.y, acc[q*4+1]);
                acc[q*4+2] = fmaf(p, v.z, acc[q*4+2]);
                acc[q*4+3] = fmaf(p, v.w, acc[q*4+3]);
            }
        }
    }
    __syncthreads();   // smem tiles done; reuse for cross-chunk combine

    float* red = sm;   // 512 threads x 18 floats = 36 KB
    {
        int slot = tid * 18;
        red[slot] = m; red[slot + 1] = l;
        #pragma unroll
        for (int u = 0; u < 16; u++) red[slot + 2 + u] = acc[u];
    }
    __syncthreads();

    if (chunk == 0) {
        const int ps = (256 + r2) * 18;
        float m1 = red[ps], l1 = red[ps + 1];
        float ms = fmaxf(m, m1);
        float e0 = __expf(m - ms), e1 = __expf(m1 - ms);
        float L = l*e0 + l1*e1;
        float inv = __frcp_rn(L);
        float o[16];
        #pragma unroll
        for (int u = 0; u < 16; u++)
            o[u] = (acc[u]*e0 + red[ps + 2 + u]*e1) * inv;
        float* op = out + (b*Nq + i)*HU + h*Uq + ub;
        #pragma unroll
        for (int q = 0; q < 4; q++)
            reinterpret_cast<float4*>(op)[q] =
                make_float4(o[q*4+0], o[q*4+1], o[q*4+2], o[q*4+3]);
    }
}

// ---------------------------------------------------------------------------
extern "C" void kernel_launch(void* const* d_in, const int* in_sizes, int n_in,
                              void* d_out, int out_size)
{
    const float* inp  = (const float*)d_in[0];   // (B,N,F)
    const float* Wsrc = (const float*)d_in[1];   // (H,F,U)
    const float* Wdst = (const float*)d_in[2];   // (H,F,U)
    const float* Av   = (const float*)d_in[3];   // (H,U,1)
    float* out = (float*)d_out;                  // (B,N,H*U)

    const int PROJ_SMEM = (64*132 + 128*64) * 4;         // 66,560 B
    const int ATTN_SMEM = (2*Nq*Uq + Nq) * 4;            // 133,120 B
    cudaFuncSetAttribute(proj_kernel,
        cudaFuncAttributeMaxDynamicSharedMemorySize, PROJ_SMEM);
    cudaFuncSetAttribute(attn_kernel,
        cudaFuncAttributeMaxDynamicSharedMemorySize, ATTN_SMEM);

    proj_kernel<<<dim3(Bq*Nq/64, Hq), 256, PROJ_SMEM>>>(inp, Wsrc, Wdst);
    cdst_kernel<<<Bq*Hq*Nq/256, 256>>>(Av);
    attn_kernel<<<dim3(Nq/128, Bq*Hq), 512, ATTN_SMEM>>>(Av, out);
}

// round 2
// speedup vs baseline: 1.1240x; 1.1240x over previous
#include <cuda_runtime.h>

#define Bq 8
#define Nq 512
#define Fq 128
#define Hq 4
#define Uq 32
#define HU (Hq*Uq)

typedef unsigned long long u64;

// ---- packed f32x2 helpers (sm_103a; ptxas won't auto-fuse, PTX only) ------
__device__ __forceinline__ u64 pk2(float lo, float hi) {
    u64 r; asm("mov.b64 %0,{%1,%2};" : "=l"(r) : "f"(lo), "f"(hi)); return r;
}
__device__ __forceinline__ void upk2(u64 v, float& lo, float& hi) {
    asm("mov.b64 {%0,%1},%2;" : "=f"(lo), "=f"(hi) : "l"(v));
}
__device__ __forceinline__ u64 add2(u64 a, u64 b) {
    u64 r; asm("add.rn.f32x2 %0,%1,%2;" : "=l"(r) : "l"(a), "l"(b)); return r;
}
__device__ __forceinline__ u64 mul2(u64 a, u64 b) {
    u64 r; asm("mul.rn.f32x2 %0,%1,%2;" : "=l"(r) : "l"(a), "l"(b)); return r;
}
__device__ __forceinline__ u64 fma2(u64 a, u64 b, u64 c) {
    u64 r; asm("fma.rn.f32x2 %0,%1,%2,%3;" : "=l"(r) : "l"(a), "l"(b), "l"(c)); return r;
}
__device__ __forceinline__ u64 relu2(u64 v) {
    float lo, hi; upk2(v, lo, hi);
    return pk2(fmaxf(lo, 0.f), fmaxf(hi, 0.f));   // 2x FMNMX on alu pipe
}

// Scratch (device globals: allocation-free)
__device__ float g_Hsrc[Bq*Hq*Nq*Uq];   // 2 MB
__device__ float g_Hdst[Bq*Hq*Nq*Uq];   // 2 MB

// ---------------------------------------------------------------------------
// Kernel 1: projections. 128-row x 64-col tiles, grid (32, H) = 128 CTAs
// (one full wave), 512 threads. FFMA2 math, float4 rv loads over k.
// ---------------------------------------------------------------------------
__global__ void __launch_bounds__(512)
proj_kernel(const float* __restrict__ inp,
            const float* __restrict__ Wsrc,
            const float* __restrict__ Wdst)
{
    extern __shared__ float sm[];
    float* sIn = sm;             // [128][132]  (pad kills conflicts; 132%4==0)
    float* sW  = sm + 128*132;   // [128][64]   (cols 0-31 src, 32-63 dst)

    const int tid  = threadIdx.x;
    const int h    = blockIdx.y;
    const int row0 = blockIdx.x * 128;

    for (int t = tid; t < 128*32; t += 512) {
        int r = t >> 5, c = t & 31;
        reinterpret_cast<float4*>(sIn + r*132)[c] =
            reinterpret_cast<const float4*>(inp + (row0 + r)*Fq)[c];
    }
    for (int t = tid; t < 128*8; t += 512) {
        int k = t >> 3, c = t & 7;
        reinterpret_cast<float4*>(sW + k*64)[c] =
            reinterpret_cast<const float4*>(Wsrc + (h*Fq + k)*Uq)[c];
        reinterpret_cast<float4*>(sW + k*64 + 32)[c] =
            reinterpret_cast<const float4*>(Wdst + (h*Fq + k)*Uq)[c];
    }
    __syncthreads();

    const int tx = tid & 15;   // 4 cols each
    const int ty = tid >> 4;   // 0..31, 4 rows each

    u64 acc[4][2];
    #pragma unroll
    for (int r = 0; r < 4; r++) { acc[r][0] = 0ull; acc[r][1] = 0ull; }

    for (int k0 = 0; k0 < 128; k0 += 4) {
        float rvr[4][4];
        #pragma unroll
        for (int r = 0; r < 4; r++) {
            float4 v = *reinterpret_cast<const float4*>(sIn + (ty*4 + r)*132 + k0);
            rvr[r][0] = v.x; rvr[r][1] = v.y; rvr[r][2] = v.z; rvr[r][3] = v.w;
        }
        #pragma unroll
        for (int kk = 0; kk < 4; kk++) {
            float4 cv = reinterpret_cast<const float4*>(sW + (k0 + kk)*64)[tx];
            u64 c01 = pk2(cv.x, cv.y), c23 = pk2(cv.z, cv.w);
            #pragma unroll
            for (int r = 0; r < 4; r++) {
                u64 rp = pk2(rvr[r][kk], rvr[r][kk]);
                acc[r][0] = fma2(rp, c01, acc[r][0]);
                acc[r][1] = fma2(rp, c23, acc[r][1]);
            }
        }
    }

    const int b = row0 >> 9;                    // 128 | 512
    float* dstp = (tx < 8) ? g_Hsrc : g_Hdst;
    const int c4 = tx & 7;
    #pragma unroll
    for (int r = 0; r < 4; r++) {
        int n = (row0 + ty*4 + r) & (Nq - 1);
        float o0, o1, o2v, o3; upk2(acc[r][0], o0, o1); upk2(acc[r][1], o2v, o3);
        reinterpret_cast<float4*>(dstp + ((b*Hq + h)*Nq + n)*Uq)[c4] =
            make_float4(o0, o1, o2v, o3);
    }
}

// ---------------------------------------------------------------------------
// Kernel 2: fused attention (c_dst computed in-kernel from the smem tile).
// grid (4 i-blocks, 32 bh), 512 threads = 128 rows x 2 u-halves x 2 j-chunks.
// score'[i,j] = c_dst[j] + sum_u (0.8*a_u) * max(s_iu + d_ju, 0)
// ---------------------------------------------------------------------------
__global__ void __launch_bounds__(512, 1)
attn_kernel(const float* __restrict__ Av, float* __restrict__ out)
{
    extern __shared__ float sm[];
    float* sh_src = sm;               // [512][32]
    float* sh_dst = sm + Nq*Uq;       // [512][32]
    float* sh_c   = sm + 2*Nq*Uq;     // [512]

    const int tid = threadIdx.x;
    const int bh  = blockIdx.y;
    const int ib  = blockIdx.x;
    const int b   = bh >> 2;
    const int h   = bh & 3;

    const float* Hs = g_Hsrc + bh*Nq*Uq;
    const float* Hd = g_Hdst + bh*Nq*Uq;
    for (int t = tid; t < Nq*Uq/4; t += 512) {
        reinterpret_cast<float4*>(sh_src)[t] = reinterpret_cast<const float4*>(Hs)[t];
        reinterpret_cast<float4*>(sh_dst)[t] = reinterpret_cast<const float4*>(Hd)[t];
    }
    __syncthreads();

    // c_dst[j] = 0.2 * sum_u a_u * h_dst[j,u], one j per thread
    {
        const float4* dr = reinterpret_cast<const float4*>(sh_dst + tid*Uq);
        const float4* ar = reinterpret_cast<const float4*>(Av + h*Uq);
        float s = 0.f;
        #pragma unroll
        for (int q = 0; q < 8; q++) {
            float4 d = dr[q], a = ar[q];
            s += d.x*a.x + d.y*a.y + d.z*a.z + d.w*a.w;
        }
        sh_c[tid] = 0.2f * s;
    }
    __syncthreads();

    const int chunk = tid >> 8;        // j in [chunk*256, +256)
    const int r2    = tid & 255;
    const int row   = r2 >> 1;
    const int uh    = r2 & 1;          // shfl partner = lane^1
    const int i     = ib*128 + row;
    const int ub    = uh*16;

    u64 s2[8], a2p[8], acc[8];
    {
        const float4* sp = reinterpret_cast<const float4*>(sh_src + i*Uq + ub);
        const float4* ap = reinterpret_cast<const float4*>(Av + h*Uq + ub);
        #pragma unroll
        for (int q = 0; q < 4; q++) {
            float4 v = sp[q];
            s2[2*q]   = pk2(v.x, v.y);
            s2[2*q+1] = pk2(v.z, v.w);
            float4 a = ap[q];
            a2p[2*q]   = pk2(0.8f*a.x, 0.8f*a.y);
            a2p[2*q+1] = pk2(0.8f*a.z, 0.8f*a.w);
        }
    }
    #pragma unroll
    for (int q = 0; q < 8; q++) acc[q] = 0ull;

    float m = -1e30f, l = 0.f;
    const int j0 = chunk * 256;

    for (int jb = 0; jb < 256; jb += 8) {
        float sc[8];
        #pragma unroll
        for (int t = 0; t < 8; t++) {
            const int j = j0 + jb + t;
            const float4* dp = reinterpret_cast<const float4*>(sh_dst + j*Uq + ub);
            u64 p2 = 0ull;
            #pragma unroll
            for (int q = 0; q < 4; q++) {
                float4 d = dp[q];
                p2 = fma2(a2p[2*q],   relu2(add2(s2[2*q],   pk2(d.x, d.y))), p2);
                p2 = fma2(a2p[2*q+1], relu2(add2(s2[2*q+1], pk2(d.z, d.w))), p2);
            }
            float plo, phi; upk2(p2, plo, phi);
            float ps = plo + phi;
            ps += __shfl_xor_sync(0xffffffffu, ps, 1);
            sc[t] = ps + sh_c[j];
        }
        float bm = sc[0];
        #pragma unroll
        for (int t = 1; t < 8; t++) bm = fmaxf(bm, sc[t]);
        float mn = fmaxf(m, bm);
        float scale = __expf(m - mn);
        m = mn;
        l *= scale;
        u64 sclp = pk2(scale, scale);
        #pragma unroll
        for (int q = 0; q < 8; q++) acc[q] = mul2(acc[q], sclp);
        #pragma unroll
        for (int t = 0; t < 8; t++) {
            float p = __expf(sc[t] - m);
            l += p;
            u64 pp = pk2(p, p);
            const float4* vp =
                reinterpret_cast<const float4*>(sh_src + (j0 + jb + t)*Uq + ub);
            #pragma unroll
            for (int q = 0; q < 4; q++) {
                float4 v = vp[q];
                acc[2*q]   = fma2(pp, pk2(v.x, v.y), acc[2*q]);
                acc[2*q+1] = fma2(pp, pk2(v.z, v.w), acc[2*q+1]);
            }
        }
    }
    __syncthreads();   // tiles done; reuse smem for cross-chunk combine

    float* red = sm;   // 512 x 18 floats
    {
        int slot = tid * 18;
        red[slot] = m; red[slot + 1] = l;
        u64* rq = reinterpret_cast<u64*>(red + slot + 2);   // 8B-aligned
        #pragma unroll
        for (int q = 0; q < 8; q++) rq[q] = acc[q];
    }
    __syncthreads();

    if (chunk == 0) {
        const int ps_ = (256 + r2) * 18;
        float m1 = red[ps_], l1 = red[ps_ + 1];
        const u64* rq1 = reinterpret_cast<const u64*>(red + ps_ + 2);
        float ms = fmaxf(m, m1);
        float e0 = __expf(m - ms), e1 = __expf(m1 - ms);
        float L = l*e0 + l1*e1;
        float inv = __frcp_rn(L);
        float f0 = e0 * inv, f1 = e1 * inv;
        u64 f0p = pk2(f0, f0), f1p = pk2(f1, f1);
        float* op = out + (b*Nq + i)*HU + h*Uq + ub;
        #pragma unroll
        for (int q = 0; q < 4; q++) {
            u64 oa = fma2(rq1[2*q],   f1p, mul2(acc[2*q],   f0p));
            u64 ob = fma2(rq1[2*q+1], f1p, mul2(acc[2*q+1], f0p));
            float x0, x1, x2, x3; upk2(oa, x0, x1); upk2(ob, x2, x3);
            reinterpret_cast<float4*>(op)[q] = make_float4(x0, x1, x2, x3);
        }
    }
}

// ---------------------------------------------------------------------------
extern "C" void kernel_launch(void* const* d_in, const int* in_sizes, int n_in,
                              void* d_out, int out_size)
{
    const float* inp  = (const float*)d_in[0];   // (B,N,F)
    const float* Wsrc = (const float*)d_in[1];   // (H,F,U)
    const float* Wdst = (const float*)d_in[2];   // (H,F,U)
    const float* Av   = (const float*)d_in[3];   // (H,U,1)
    float* out = (float*)d_out;                  // (B,N,H*U)

    const int PROJ_SMEM = (128*132 + 128*64) * 4;        // 100,352 B
    const int ATTN_SMEM = (2*Nq*Uq + Nq) * 4;            // 133,120 B
    cudaFuncSetAttribute(proj_kernel,
        cudaFuncAttributeMaxDynamicSharedMemorySize, PROJ_SMEM);
    cudaFuncSetAttribute(attn_kernel,
        cudaFuncAttributeMaxDynamicSharedMemorySize, ATTN_SMEM);

    proj_kernel<<<dim3(Bq*Nq/128, Hq), 512, PROJ_SMEM>>>(inp, Wsrc, Wdst);
    attn_kernel<<<dim3(Nq/128, Bq*Hq), 512, ATTN_SMEM>>>(Av, out);
}